// round 11
// baseline (speedup 1.0000x reference)
#include <cuda_runtime.h>
#include <cuda_bf16.h>
#include <cstdint>
#include <cstddef>
#include <math.h>

// Problem constants
#define B    32
#define S    64
#define T    64
#define E    512
#define H    1024
#define VT   32000
#define TWOE 1024
#define FOURH 4096
#define NCTA 128          // persistent recurrence CTAs (<= SM count, all resident)

// ---------------- scratch (device globals) ----------------
__device__ float g_enc[B * S * TWOE];                 // [b*S+s][1024]
__device__ float g_encmean[B * TWOE];
__device__ float g_h[B * H];
__device__ float g_c[B * H];
__device__ float g_attw[B * S];
__device__ float g_bsum[FOURH];
__device__ float g_gatesw[(size_t)B * T * FOURH];     // row r=t*B+b
__device__ float g_encprojT[(size_t)FOURH * B * S];   // [n][b*S+s]
__device__ float g_gpart[8 * B * FOURH];              // 8 k-slice partials
__device__ unsigned g_cnt = 0;
__device__ unsigned g_gen = 0;
// bf16 hi/lo operand buffers
__device__ __nv_bfloat16 g_encHi[(size_t)B * S * TWOE];
__device__ __nv_bfloat16 g_encLo[(size_t)B * S * TWOE];
__device__ __nv_bfloat16 g_wrdHi[(size_t)B * T * E];  // row r=t*B+b
__device__ __nv_bfloat16 g_wrdLo[(size_t)B * T * E];
__device__ __nv_bfloat16 g_hsHi[(size_t)B * T * H];   // row r=b*T+t
__device__ __nv_bfloat16 g_hsLo[(size_t)B * T * H];
__device__ __nv_bfloat16 g_WoHi[(size_t)VT * H];
__device__ __nv_bfloat16 g_WoLo[(size_t)VT * H];
__device__ __nv_bfloat16 g_WcHi[(size_t)FOURH * H];   // W_ih[:,512:1536]
__device__ __nv_bfloat16 g_WcLo[(size_t)FOURH * H];
__device__ __nv_bfloat16 g_WwHi[(size_t)FOURH * E];   // W_ih[:,0:512]
__device__ __nv_bfloat16 g_WwLo[(size_t)FOURH * E];

// ---------------- asm helpers ----------------
__device__ __forceinline__ uint32_t s2u(const void* p) {
    uint32_t a;
    asm("{ .reg .u64 t; cvta.to.shared.u64 t, %1; cvt.u32.u64 %0, t; }" : "=r"(a) : "l"(p));
    return a;
}
__device__ __forceinline__ void cp16(uint32_t saddr, const void* g) {
    asm volatile("cp.async.cg.shared.global [%0], [%1], 16;" :: "r"(saddr), "l"(g));
}
__device__ __forceinline__ void cp_commit() {
    asm volatile("cp.async.commit_group;" ::: "memory");
}
__device__ __forceinline__ void cp_wait2() {
    asm volatile("cp.async.wait_group 2;" ::: "memory");
}
__device__ __forceinline__ void ldsm_x4(uint32_t* r, uint32_t addr) {
    asm volatile("ldmatrix.sync.aligned.m8n8.x4.shared.b16 {%0,%1,%2,%3}, [%4];"
                 : "=r"(r[0]), "=r"(r[1]), "=r"(r[2]), "=r"(r[3]) : "r"(addr));
}
__device__ __forceinline__ void ldsm_x2(uint32_t* r, uint32_t addr) {
    asm volatile("ldmatrix.sync.aligned.m8n8.x2.shared.b16 {%0,%1}, [%2];"
                 : "=r"(r[0]), "=r"(r[1]) : "r"(addr));
}
__device__ __forceinline__ void mma16816(float* d, const uint32_t* a, const uint32_t* b) {
    asm volatile("mma.sync.aligned.m16n8k16.row.col.f32.bf16.bf16.f32 "
                 "{%0,%1,%2,%3}, {%4,%5,%6,%7}, {%8,%9}, {%0,%1,%2,%3};"
                 : "+f"(d[0]), "+f"(d[1]), "+f"(d[2]), "+f"(d[3])
                 : "r"(a[0]), "r"(a[1]), "r"(a[2]), "r"(a[3]), "r"(b[0]), "r"(b[1]));
}
__device__ __forceinline__ uint32_t swz(int r, int c) {
    return (uint32_t)(r * 64 + ((((c + (r >> 2)) & 3) ^ (r & 3)) << 4));
}
__device__ __forceinline__ float sigm(float x) { return 1.f / (1.f + expf(-x)); }

// sense-free generation barrier across NCTA resident CTAs
__device__ __forceinline__ void gridbar(unsigned& mygen) {
    __syncthreads();
    if (threadIdx.x == 0) {
        __threadfence();
        if (atomicAdd(&g_cnt, 1u) == NCTA - 1) {
            g_cnt = 0;
            __threadfence();
            atomicAdd(&g_gen, 1u);
        } else {
            while (*((volatile unsigned*)&g_gen) == mygen) { }
        }
        __threadfence();
    }
    __syncthreads();
    mygen++;
}

// ---------------- prep kernels ----------------

__global__ void __launch_bounds__(256) k_prep_enc(const int* __restrict__ src,
                                                  const int* __restrict__ pos,
                                                  const float* __restrict__ enc_emb,
                                                  const float* __restrict__ pos_emb) {
    int bs = blockIdx.x;
    int w = src[bs], p = pos[bs];
    int j = threadIdx.x * 4;
    const float* sp = (j < 512) ? (enc_emb + (size_t)w * E + j)
                                : (pos_emb + (size_t)p * E + (j - 512));
    float4 v = *(const float4*)sp;
    size_t o = (size_t)bs * TWOE + j;
    *(float4*)(g_enc + o) = v;
    float a[4]; a[0] = v.x; a[1] = v.y; a[2] = v.z; a[3] = v.w;
    __nv_bfloat16 h4[4], l4[4];
    #pragma unroll
    for (int i = 0; i < 4; i++) {
        __nv_bfloat16 bh = __float2bfloat16_rn(a[i]);
        h4[i] = bh;
        l4[i] = __float2bfloat16_rn(a[i] - __bfloat162float(bh));
    }
    *(uint2*)(g_encHi + o) = *(uint2*)h4;
    *(uint2*)(g_encLo + o) = *(uint2*)l4;
}

__global__ void __launch_bounds__(128) k_prep_words(const int* __restrict__ ts,
                                                    const float* __restrict__ dec_emb) {
    int r = blockIdx.x;
    int t = r / B, b = r % B;
    int w = ts[b * T + t];
    int j = threadIdx.x * 4;
    float4 v = *(const float4*)(dec_emb + (size_t)w * E + j);
    float a[4]; a[0] = v.x; a[1] = v.y; a[2] = v.z; a[3] = v.w;
    __nv_bfloat16 h4[4], l4[4];
    #pragma unroll
    for (int i = 0; i < 4; i++) {
        __nv_bfloat16 bh = __float2bfloat16_rn(a[i]);
        h4[i] = bh;
        l4[i] = __float2bfloat16_rn(a[i] - __bfloat162float(bh));
    }
    size_t o = (size_t)r * E + j;
    *(uint2*)(g_wrdHi + o) = *(uint2*)h4;
    *(uint2*)(g_wrdLo + o) = *(uint2*)l4;
}

__global__ void k_cvt_rows(const float* __restrict__ src, int srcStride,
                           __nv_bfloat16* __restrict__ hi, __nv_bfloat16* __restrict__ lo,
                           int ncols) {
    int r = blockIdx.x;
    int j = threadIdx.x * 4;
    float4 v = *(const float4*)(src + (size_t)r * srcStride + j);
    float a[4]; a[0] = v.x; a[1] = v.y; a[2] = v.z; a[3] = v.w;
    __nv_bfloat16 h4[4], l4[4];
    #pragma unroll
    for (int i = 0; i < 4; i++) {
        __nv_bfloat16 bh = __float2bfloat16_rn(a[i]);
        h4[i] = bh;
        l4[i] = __float2bfloat16_rn(a[i] - __bfloat162float(bh));
    }
    size_t o = (size_t)r * ncols + j;
    *(uint2*)(hi + o) = *(uint2*)h4;
    *(uint2*)(lo + o) = *(uint2*)l4;
}

__global__ void __launch_bounds__(256) k_bsum(const float* __restrict__ b_ih,
                                              const float* __restrict__ b_hh) {
    int i = blockIdx.x * 256 + threadIdx.x;
    g_bsum[i] = b_ih[i] + b_hh[i];
}

__global__ void __launch_bounds__(1024) k_encmean() {
    int b = blockIdx.x, d = threadIdx.x;
    float s = 0.f;
    const float* base = g_enc + (size_t)b * S * TWOE + d;
    #pragma unroll 8
    for (int i = 0; i < S; i++) s += base[(size_t)i * TWOE];
    g_encmean[b * TWOE + d] = s * (1.0f / S);
}

__global__ void __launch_bounds__(256) k_h0(const float* __restrict__ W_h0,
                                            const float* __restrict__ b_h0) {
    int gid = blockIdx.x * 8 + (threadIdx.x >> 5);
    int lane = threadIdx.x & 31;
    int b = gid >> 10, n = gid & 1023;
    const float* a = g_encmean + b * 1024;
    const float* w = W_h0 + (size_t)n * 1024;
    float acc = 0.f;
    for (int k = lane; k < 1024; k += 32) acc += a[k] * w[k];
    #pragma unroll
    for (int o = 16; o; o >>= 1) acc += __shfl_xor_sync(0xffffffffu, acc, o);
    if (lane == 0) {
        float v = acc + b_h0[n];
        g_h[b * H + n] = v;
        g_c[b * H + n] = v;
    }
}

// ---------------- generalized bf16 HMMA 3-pass GEMM (2 CTAs/SM) ----------------
#define PSTG 32768
#define HMMA_SMEM (3 * PSTG)

__global__ void __launch_bounds__(256, 2) k_hmma(
    const __nv_bfloat16* __restrict__ Ahi, const __nv_bfloat16* __restrict__ Alo,
    const __nv_bfloat16* __restrict__ Bhi, const __nv_bfloat16* __restrict__ Blo,
    const float* __restrict__ bias, float* __restrict__ C, int K, int ldc)
{
    extern __shared__ __align__(128) char smem[];
    const uint32_t sb = s2u(smem);
    int tid = threadIdx.x, lane = tid & 31, wid = tid >> 5;
    int wm = wid & 1, wn = wid >> 1;
    int m0 = blockIdx.x * 128;
    int n0 = blockIdx.y * 128;
    int nIter = K >> 5;

    float acc[4][4][4];
    #pragma unroll
    for (int i = 0; i < 4; i++) {
        #pragma unroll
        for (int j = 0; j < 4; j++) {
            #pragma unroll
            for (int v = 0; v < 4; v++) acc[i][j][v] = 0.f;
        }
    }

    int lr = tid >> 2;
    int lc = tid & 3;
    uint32_t so0 = swz(lr, lc);
    uint32_t so1 = swz(lr + 64, lc);
    const char* gA0h = (const char*)(Ahi + (size_t)(m0 + lr) * K + lc * 8);
    const char* gA1h = (const char*)(Ahi + (size_t)(m0 + lr + 64) * K + lc * 8);
    const char* gA0l = (const char*)(Alo + (size_t)(m0 + lr) * K + lc * 8);
    const char* gA1l = (const char*)(Alo + (size_t)(m0 + lr + 64) * K + lc * 8);
    const char* gB0h = (const char*)(Bhi + (size_t)(n0 + lr) * K + lc * 8);
    const char* gB1h = (const char*)(Bhi + (size_t)(n0 + lr + 64) * K + lc * 8);
    const char* gB0l = (const char*)(Blo + (size_t)(n0 + lr) * K + lc * 8);
    const char* gB1l = (const char*)(Blo + (size_t)(n0 + lr + 64) * K + lc * 8);

    #define ISSUE(ST, K0) do { uint32_t s0 = sb + (uint32_t)(ST) * PSTG; \
        size_t kb = (size_t)(K0) * 2; \
        cp16(s0 + so0,          gA0h + kb); cp16(s0 + so1,          gA1h + kb); \
        cp16(s0 + 8192  + so0,  gA0l + kb); cp16(s0 + 8192  + so1,  gA1l + kb); \
        cp16(s0 + 16384 + so0,  gB0h + kb); cp16(s0 + 16384 + so1,  gB1h + kb); \
        cp16(s0 + 24576 + so0,  gB0l + kb); cp16(s0 + 24576 + so1,  gB1l + kb); } while (0)

    ISSUE(0, 0);  cp_commit();
    ISSUE(1, 32); cp_commit();
    ISSUE(2, 64); cp_commit();

    int arow = lane & 15;
    int aselh = lane >> 4;
    int brow = lane & 7;
    int bselh = (lane >> 3) & 1;

    for (int it = 0; it < nIter; ++it) {
        cp_wait2();
        __syncthreads();
        int st = it - (it / 3) * 3;
        uint32_t stA_hi = sb + (uint32_t)st * PSTG;
        uint32_t stA_lo = stA_hi + 8192;
        uint32_t stB_hi = stA_hi + 16384;
        uint32_t stB_lo = stA_hi + 24576;
        #pragma unroll
        for (int ks = 0; ks < 2; ++ks) {
            int c0 = ks * 2;
            uint32_t ah[4][4], al[4][4], bh[4][2], bl[4][2];
            #pragma unroll
            for (int mt = 0; mt < 4; mt++) {
                int r = wm * 64 + mt * 16 + arow;
                uint32_t off = swz(r, c0 + aselh);
                ldsm_x4(ah[mt], stA_hi + off);
                ldsm_x4(al[mt], stA_lo + off);
            }
            #pragma unroll
            for (int nt = 0; nt < 4; nt++) {
                int r = wn * 32 + nt * 8 + brow;
                uint32_t off = swz(r, c0 + bselh);
                ldsm_x2(bh[nt], stB_hi + off);
                ldsm_x2(bl[nt], stB_lo + off);
            }
            #pragma unroll
            for (int mt = 0; mt < 4; mt++) {
                #pragma unroll
                for (int nt = 0; nt < 4; nt++) {
                    mma16816(acc[mt][nt], ah[mt], bh[nt]);
                    mma16816(acc[mt][nt], ah[mt], bl[nt]);
                    mma16816(acc[mt][nt], al[mt], bh[nt]);
                }
            }
        }
        __syncthreads();
        if (it + 3 < nIter) ISSUE(st, (it + 3) * 32);
        cp_commit();
    }
    #undef ISSUE

    #pragma unroll
    for (int nt = 0; nt < 4; nt++) {
        int col = n0 + wn * 32 + nt * 8 + (lane & 3) * 2;
        float b0 = 0.f, b1 = 0.f;
        if (bias) { b0 = bias[col]; b1 = bias[col + 1]; }
        #pragma unroll
        for (int mt = 0; mt < 4; mt++) {
            int row = m0 + wm * 64 + mt * 16 + (lane >> 2);
            float* c0p = C + (size_t)row * ldc + col;
            float* c1p = C + (size_t)(row + 8) * ldc + col;
            c0p[0] = acc[mt][nt][0] + b0;
            c0p[1] = acc[mt][nt][1] + b1;
            c1p[0] = acc[mt][nt][2] + b0;
            c1p[1] = acc[mt][nt][3] + b1;
        }
    }
}

// ---------------- persistent recurrence kernel ----------------
// grid = NCTA(128) x 256 threads, all co-resident; software grid barrier.
// Per step: phase G (gates partials: 16 n-tiles x 8 k-slices of W_hh GEMM + encsum)
//           -> barrier -> phase L (CTA b<32: reduce+LSTM+attention) -> barrier.
__global__ void __launch_bounds__(256) k_recur(const float* __restrict__ W_hh,
                                               const int* __restrict__ sl) {
    __shared__ float sH[128][36];     // h^T slice  [k][b]
    __shared__ float sW[16][260];     // W chunk    [k][n]
    __shared__ float sAw[B][8];       // attw slice [b][s_local]
    __shared__ float sHb[1024];       // phase L: h vector of this CTA's b
    __shared__ float se[64];

    int cta = blockIdx.x, tid = threadIdx.x;
    unsigned mygen = *((volatile unsigned*)&g_gen);
    int nt = cta >> 3;                // 0..15
    int ksl = cta & 7;                // 0..7
    int n0 = nt << 8;                 // 256-wide n tile
    int k0 = ksl << 7;                // 128-wide k slice
    int s0 = ksl << 3;                // 8-wide s slice for encsum
    int bg = tid >> 5, ng = tid & 31; // 4b x 8n register tile
    int b0 = bg << 2, nn = ng << 3;
    int warp = tid >> 5, lane = tid & 31;

    // ---- initial attention from h0 (CTA b < 32) ----
    if (cta < B) {
        int b = cta;
        for (int q = 0; q < 4; q++) sHb[q * 256 + tid] = g_h[b * H + q * 256 + tid];
        __syncthreads();
        #pragma unroll
        for (int q = 0; q < 8; q++) {
            int s = warp * 8 + q;
            const float* er = g_enc + ((size_t)b * S + s) * TWOE;
            float acc = 0.f;
            #pragma unroll 8
            for (int k = lane; k < TWOE; k += 32) acc += er[k] * sHb[k];
            #pragma unroll
            for (int o = 16; o; o >>= 1) acc += __shfl_xor_sync(0xffffffffu, acc, o);
            if (lane == 0) se[s] = acc;
        }
        __syncthreads();
        if (warp == 0) {
            int len = sl[b];
            float e0 = se[lane], e1 = se[lane + 32];
            float m = fmaxf(e0, e1);
            #pragma unroll
            for (int o = 16; o; o >>= 1) m = fmaxf(m, __shfl_xor_sync(0xffffffffu, m, o));
            float p0 = (lane < len)      ? expf(e0 - m) : 0.f;
            float p1 = (lane + 32 < len) ? expf(e1 - m) : 0.f;
            float ssum = p0 + p1;
            #pragma unroll
            for (int o = 16; o; o >>= 1) ssum += __shfl_xor_sync(0xffffffffu, ssum, o);
            float inv = 1.f / ssum;
            g_attw[b * S + lane] = p0 * inv;
            g_attw[b * S + lane + 32] = p1 * inv;
        }
    }
    gridbar(mygen);

    for (int t = 0; t < T; t++) {
        // ================= phase G =================
        // load h^T slice: warp-coalesced (b = tid>>3, 16-float segs)
        {
            int b = tid >> 3, seg = tid & 7;
            const float4* hp = (const float4*)(g_h + (size_t)b * H + k0 + seg * 16);
            #pragma unroll
            for (int i = 0; i < 4; i++) {
                float4 v = hp[i];
                int kk = seg * 16 + i * 4;
                sH[kk + 0][b] = v.x; sH[kk + 1][b] = v.y;
                sH[kk + 2][b] = v.z; sH[kk + 3][b] = v.w;
            }
        }
        { int b = tid >> 3, s = tid & 7; sAw[b][s] = g_attw[b * S + s0 + s]; }

        float acc[4][8];
        #pragma unroll
        for (int i = 0; i < 4; i++) {
            #pragma unroll
            for (int j = 0; j < 8; j++) acc[i][j] = 0.f;
        }

        for (int kc = 0; kc < 8; kc++) {
            // load W chunk [16k x 256n], 64B-coalesced, transposed into sW
            #pragma unroll
            for (int pp = 0; pp < 4; pp++) {
                int row = pp * 64 + (tid >> 2);          // n within tile
                int cseg = tid & 3;                      // 4-float seg of the 16 k
                float4 w = *(const float4*)(W_hh + (size_t)(n0 + row) * H + k0 + kc * 16 + cseg * 4);
                sW[cseg * 4 + 0][row] = w.x;
                sW[cseg * 4 + 1][row] = w.y;
                sW[cseg * 4 + 2][row] = w.z;
                sW[cseg * 4 + 3][row] = w.w;
            }
            __syncthreads();
            #pragma unroll
            for (int kk = 0; kk < 16; kk++) {
                float4 hv = *(const float4*)&sH[kc * 16 + kk][b0];
                float wv[8];
                *(float4*)(wv)     = *(const float4*)&sW[kk][nn];
                *(float4*)(wv + 4) = *(const float4*)&sW[kk][nn + 4];
                float ha[4]; ha[0] = hv.x; ha[1] = hv.y; ha[2] = hv.z; ha[3] = hv.w;
                #pragma unroll
                for (int i = 0; i < 4; i++) {
                    #pragma unroll
                    for (int j = 0; j < 8; j++) acc[i][j] += ha[i] * wv[j];
                }
            }
            __syncthreads();
        }

        // encsum contribution for this CTA's 8 s-values + store partials
        #pragma unroll
        for (int i = 0; i < 4; i++) {
            int b = b0 + i;
            float aw[8];
            *(float4*)(aw)     = *(const float4*)&sAw[b][0];
            *(float4*)(aw + 4) = *(const float4*)&sAw[b][4];
            float* gp = g_gpart + (size_t)ksl * (B * FOURH) + (size_t)b * FOURH + n0 + nn;
            #pragma unroll
            for (int j = 0; j < 8; j++) {
                const float* e = g_encprojT + (size_t)(n0 + nn + j) * (B * S) + b * S + s0;
                float4 e0 = *(const float4*)e;
                float4 e1 = *(const float4*)(e + 4);
                float v = acc[i][j]
                    + aw[0] * e0.x + aw[1] * e0.y + aw[2] * e0.z + aw[3] * e0.w
                    + aw[4] * e1.x + aw[5] * e1.y + aw[6] * e1.z + aw[7] * e1.w;
                gp[j] = v;
            }
        }
        gridbar(mygen);

        // ================= phase L =================
        if (cta < B) {
            int b = cta;
            const float* gw = g_gatesw + ((size_t)t * B + b) * FOURH;
            #pragma unroll
            for (int q = 0; q < 4; q++) {
                int n = q * 256 + tid;
                float gi = gw[n], gf = gw[n + 1024], gg = gw[n + 2048], go = gw[n + 3072];
                #pragma unroll
                for (int s8 = 0; s8 < 8; s8++) {
                    const float* gp = g_gpart + (size_t)s8 * (B * FOURH) + (size_t)b * FOURH;
                    gi += gp[n]; gf += gp[n + 1024]; gg += gp[n + 2048]; go += gp[n + 3072];
                }
                float c = g_c[b * H + n];
                float iv = sigm(gi), fv = sigm(gf), gv = tanhf(gg), ov = sigm(go);
                c = fv * c + iv * gv;
                float h = ov * tanhf(c);
                g_c[b * H + n] = c;
                g_h[b * H + n] = h;
                sHb[n] = h;
                size_t row = ((size_t)b * T + t) * H + n;
                __nv_bfloat16 hh = __float2bfloat16_rn(h);
                g_hsHi[row] = hh;
                g_hsLo[row] = __float2bfloat16_rn(h - __bfloat162float(hh));
            }
            __syncthreads();
            // attention energies + softmax for next step
            #pragma unroll
            for (int q = 0; q < 8; q++) {
                int s = warp * 8 + q;
                const float* er = g_enc + ((size_t)b * S + s) * TWOE;
                float acc2 = 0.f;
                #pragma unroll 8
                for (int k = lane; k < TWOE; k += 32) acc2 += er[k] * sHb[k];
                #pragma unroll
                for (int o = 16; o; o >>= 1) acc2 += __shfl_xor_sync(0xffffffffu, acc2, o);
                if (lane == 0) se[s] = acc2;
            }
            __syncthreads();
            if (warp == 0) {
                int len = sl[b];
                float e0 = se[lane], e1 = se[lane + 32];
                float m = fmaxf(e0, e1);
                #pragma unroll
                for (int o = 16; o; o >>= 1) m = fmaxf(m, __shfl_xor_sync(0xffffffffu, m, o));
                float p0 = (lane < len)      ? expf(e0 - m) : 0.f;
                float p1 = (lane + 32 < len) ? expf(e1 - m) : 0.f;
                float ssum = p0 + p1;
                #pragma unroll
                for (int o = 16; o; o >>= 1) ssum += __shfl_xor_sync(0xffffffffu, ssum, o);
                float inv = 1.f / ssum;
                g_attw[b * S + lane] = p0 * inv;
                g_attw[b * S + lane + 32] = p1 * inv;
            }
        }
        gridbar(mygen);
    }
}

// ---------------- host ----------------
extern "C" void kernel_launch(void* const* d_in, const int* in_sizes, int n_in,
                              void* d_out, int out_size) {
    int p = 0;
    auto nx = [&]() -> const void* {
        while (p < n_in && in_sizes[p] == 1) p++;
        return d_in[p++];
    };
    const int*   ts      = (const int*)nx();
    (void)nx();                                  // target_lengths (unused)
    const int*   sl      = (const int*)nx();
    const int*   ss      = (const int*)nx();
    const int*   pos     = (const int*)nx();
    const float* enc_emb = (const float*)nx();
    const float* pos_emb = (const float*)nx();
    const float* dec_emb = (const float*)nx();
    const float* W_h0    = (const float*)nx();
    const float* b_h0    = (const float*)nx();
    const float* W_ih    = (const float*)nx();
    const float* W_hh    = (const float*)nx();
    const float* b_ih    = (const float*)nx();
    const float* b_hh    = (const float*)nx();
    const float* W_out   = (const float*)nx();
    const float* b_out   = (const float*)nx();

    float *p_gatesw, *p_encprojT, *p_bsum;
    __nv_bfloat16 *p_encHi, *p_encLo, *p_wrdHi, *p_wrdLo, *p_hsHi, *p_hsLo;
    __nv_bfloat16 *p_WoHi, *p_WoLo, *p_WcHi, *p_WcLo, *p_WwHi, *p_WwLo;
    cudaGetSymbolAddress((void**)&p_gatesw,   g_gatesw);
    cudaGetSymbolAddress((void**)&p_encprojT, g_encprojT);
    cudaGetSymbolAddress((void**)&p_bsum,     g_bsum);
    cudaGetSymbolAddress((void**)&p_encHi,    g_encHi);
    cudaGetSymbolAddress((void**)&p_encLo,    g_encLo);
    cudaGetSymbolAddress((void**)&p_wrdHi,    g_wrdHi);
    cudaGetSymbolAddress((void**)&p_wrdLo,    g_wrdLo);
    cudaGetSymbolAddress((void**)&p_hsHi,     g_hsHi);
    cudaGetSymbolAddress((void**)&p_hsLo,     g_hsLo);
    cudaGetSymbolAddress((void**)&p_WoHi,     g_WoHi);
    cudaGetSymbolAddress((void**)&p_WoLo,     g_WoLo);
    cudaGetSymbolAddress((void**)&p_WcHi,     g_WcHi);
    cudaGetSymbolAddress((void**)&p_WcLo,     g_WcLo);
    cudaGetSymbolAddress((void**)&p_WwHi,     g_WwHi);
    cudaGetSymbolAddress((void**)&p_WwLo,     g_WwLo);

    cudaFuncSetAttribute(k_hmma, cudaFuncAttributeMaxDynamicSharedMemorySize, HMMA_SMEM);

    // ---- prep ----
    k_prep_enc  <<<B * S, 256>>>(ss, pos, enc_emb, pos_emb);
    k_prep_words<<<B * T, 128>>>(ts, dec_emb);
    k_cvt_rows  <<<VT, 256>>>(W_out, H, p_WoHi, p_WoLo, H);
    k_cvt_rows  <<<FOURH, 256>>>(W_ih + 512, 1536, p_WcHi, p_WcLo, H);
    k_cvt_rows  <<<FOURH, 128>>>(W_ih, 1536, p_WwHi, p_WwLo, E);
    k_bsum      <<<FOURH / 256, 256>>>(b_ih, b_hh);
    k_encmean   <<<B, 1024>>>();
    k_h0        <<<(B * H) / 8, 256>>>(W_h0, b_h0);
    // gates_w = words @ W_ih[:,:512]^T + (b_ih + b_hh)    [2048 x 4096], K=512
    k_hmma<<<dim3(16, FOURH / 128), 256, HMMA_SMEM>>>(
        p_wrdHi, p_wrdLo, p_WwHi, p_WwLo, p_bsum, p_gatesw, E, FOURH);
    // encprojT[n][bs] = W_ctx @ enc^T    [4096 x 2048], K=1024
    k_hmma<<<dim3(FOURH / 128, 16), 256, HMMA_SMEM>>>(
        p_WcHi, p_WcLo, p_encHi, p_encLo, nullptr, p_encprojT, H, B * S);

    // ---- sequential phase: single persistent launch ----
    k_recur<<<NCTA, 256>>>(W_hh, sl);

    // ---- output projection: hs @ W_out^T + b_out   [2048 x 32000], K=1024 ----
    k_hmma<<<dim3(16, VT / 128), 256, HMMA_SMEM>>>(
        p_hsHi, p_hsLo, p_WoHi, p_WoLo, b_out, (float*)d_out, H, VT);
}